// round 8
// baseline (speedup 1.0000x reference)
#include <cuda_runtime.h>

// SofaNetEllipse via Chebyshev spectral compression (NQ=32) — two kernels.
//
// Kernel A: exact MLP+JVP at 32 Chebyshev nodes per network (4 threads/node)
//           + DCT, writes 32 float4 coefficients per network to scratch.
// Kernel B: Clenshaw (31 iters, packed fma.rn.f32x2) at all 1025 columns +
//           square/JVP + trig epilogue + mirror. 256 thr/block, ~40 regs.

#define NAB   1024
#define NCOL  2049
#define HALF  1025
#define H     64
#define TPB   128     // kernel A
#define TPB2  256     // kernel B
#define NQ    32      // Chebyshev nodes / coefficients

#define XH    0.7853981633974483f   // pi/4  (half-width of [0, pi/2])
#define INVXH 1.2732395447351628f   // 4/pi  (s = alpha*INVXH - 1)

typedef unsigned long long u64;

__device__ __align__(16) float4 g_coef[NAB * NQ];   // 512 KB scratch

__device__ __forceinline__ float fast_tanh(float x) {
    // tanh(x) = 1 - 2/(exp(2x)+1); abs err ~1e-6, saturates correctly.
    float e = __expf(x + x);
    return 1.0f - __fdividef(2.0f, e + 1.0f);
}

__device__ __forceinline__ u64 fma2(u64 a, u64 b, u64 c) {
    u64 d;
    asm("fma.rn.f32x2 %0, %1, %2, %3;" : "=l"(d) : "l"(a), "l"(b), "l"(c));
    return d;
}
__device__ __forceinline__ u64 pack2(float lo, float hi) {
    u64 r;
    asm("mov.b64 %0, {%1, %2};" : "=l"(r) : "f"(lo), "f"(hi));
    return r;
}
__device__ __forceinline__ float2 unpack2(u64 v) {
    float2 r;
    asm("mov.b64 {%0, %1}, %2;" : "=f"(r.x), "=f"(r.y) : "l"(v));
    return r;
}

// ======================= Kernel A: coefficients =======================
__global__ __launch_bounds__(TPB)
void sofanet_coef_kernel(const float* __restrict__ w0,
                         const float* __restrict__ w1,
                         const float* __restrict__ w2,
                         const float* __restrict__ b0,
                         const float* __restrict__ b1,
                         const float* __restrict__ b2)
{
    const int n   = blockIdx.x;   // network id
    const int tid = threadIdx.x;

    __shared__ __align__(16) float  w1s[H * H];   // 16 KB
    __shared__ float w0s[H], b0s[H], b1s[H];
    __shared__ float w2s[2 * H];
    __shared__ float b2s[2];
    __shared__ __align__(16) float4 nodes[NQ];    // f(x_q) = (p0,p1,q0,q1)

    // ---- stage weights ----
    {
        const float4* src = reinterpret_cast<const float4*>(w1 + (size_t)n * H * H);
        float4* dst = reinterpret_cast<float4*>(w1s);
        #pragma unroll
        for (int i = tid; i < (H * H) / 4; i += TPB) dst[i] = src[i];

        if (tid < H) {
            w0s[tid] = w0[(size_t)n * H + tid];
            b0s[tid] = b0[(size_t)n * H + tid];
            b1s[tid] = b1[(size_t)n * H + tid];
        }
        if (tid < 2 * H) w2s[tid] = w2[(size_t)n * 2 * H + tid];
        if (tid < 2)     b2s[tid] = b2[(size_t)n * 2 + tid];
    }
    __syncthreads();

    // ---- exact MLP + JVP at 32 Chebyshev nodes (4 threads per node) ----
    {
        const int q    = tid >> 2;        // node 0..31
        const int quad = tid & 3;         // row quarter
        const float theta = (2 * q + 1) * (3.14159265358979323846f / 64.0f);
        const float xq = XH * (1.0f + cosf(theta));   // node in [0, pi/2]

        float h1[H], d1[H];
        #pragma unroll
        for (int j = 0; j < H; ++j) {
            const float w  = w0s[j];
            const float th = fast_tanh(fmaf(w, xq, b0s[j]));
            h1[j] = th;
            d1[j] = (1.0f - th * th) * w;
        }

        float p0 = 0.f, p1 = 0.f, q0 = 0.f, q1 = 0.f;
        const int i0 = quad * 16;
        #pragma unroll 2
        for (int i = i0; i < i0 + 16; ++i) {
            float u = b1s[i], v = 0.f;
            const float* ra = &w1s[i * H];
            #pragma unroll
            for (int j = 0; j < H; j += 4) {
                const float4 wa = *reinterpret_cast<const float4*>(ra + j);
                u = fmaf(wa.x, h1[j    ], u);
                u = fmaf(wa.y, h1[j + 1], u);
                u = fmaf(wa.z, h1[j + 2], u);
                u = fmaf(wa.w, h1[j + 3], u);
                v = fmaf(wa.x, d1[j    ], v);
                v = fmaf(wa.y, d1[j + 1], v);
                v = fmaf(wa.z, d1[j + 2], v);
                v = fmaf(wa.w, d1[j + 3], v);
            }
            const float th = fast_tanh(u);
            const float dd = (1.0f - th * th) * v;
            p0 = fmaf(w2s[i    ], th, p0);
            p1 = fmaf(w2s[H + i], th, p1);
            q0 = fmaf(w2s[i    ], dd, q0);
            q1 = fmaf(w2s[H + i], dd, q1);
        }

        // combine the 4 quarters (lanes 4q..4q+3, same warp)
        p0 += __shfl_xor_sync(0xFFFFFFFFu, p0, 1);
        p1 += __shfl_xor_sync(0xFFFFFFFFu, p1, 1);
        q0 += __shfl_xor_sync(0xFFFFFFFFu, q0, 1);
        q1 += __shfl_xor_sync(0xFFFFFFFFu, q1, 1);
        p0 += __shfl_xor_sync(0xFFFFFFFFu, p0, 2);
        p1 += __shfl_xor_sync(0xFFFFFFFFu, p1, 2);
        q0 += __shfl_xor_sync(0xFFFFFFFFu, q0, 2);
        q1 += __shfl_xor_sync(0xFFFFFFFFu, q1, 2);

        if (quad == 0)
            nodes[q] = make_float4(p0 + b2s[0], p1 + b2s[1], q0, q1);
    }
    __syncthreads();

    // ---- DCT -> Chebyshev coefficients (threads 0..31) -> global ----
    if (tid < NQ) {
        const int k = tid;
        float s0 = 0.f, s1 = 0.f, s2 = 0.f, s3 = 0.f;
        #pragma unroll 8
        for (int q = 0; q < NQ; ++q) {
            const int m = (k * (2 * q + 1)) & 127;   // angle mod 2*pi
            const float c = __cosf((float)m * (3.14159265358979323846f / 64.0f));
            const float4 f = nodes[q];
            s0 = fmaf(c, f.x, s0);
            s1 = fmaf(c, f.y, s1);
            s2 = fmaf(c, f.z, s2);
            s3 = fmaf(c, f.w, s3);
        }
        const float sc = (k == 0) ? (1.0f / NQ) : (2.0f / NQ);
        g_coef[n * NQ + k] = make_float4(s0 * sc, s1 * sc, s2 * sc, s3 * sc);
    }
}

// ======================= Kernel B: evaluation =========================
__global__ __launch_bounds__(TPB2, 6)
void sofanet_eval_kernel(const float* __restrict__ alpha,
                         float* __restrict__ out)
{
    const int n   = blockIdx.x;   // network id
    const int tid = threadIdx.x;

    __shared__ __align__(16) float4 coef[NQ];   // 512 B
    __shared__ float xlast_s;

    // stage coefficients (128 floats, coalesced)
    if (tid < NQ * 4) {
        const float* src = (const float*)(g_coef + (size_t)n * NQ);
        ((float*)coef)[tid] = src[tid];
    }
    __syncthreads();

    const size_t AR  = (size_t)NAB * NCOL;
    const size_t row = (size_t)n * NCOL;
    float xlast = 0.0f;
    (void)xlast;

    const u64 NEG1 = pack2(-1.0f, -1.0f);

    // 5 strided tiles cover m = 0..1024 (TPB2=256); remap so m=0 -> t=1024.
    for (int k = 0; k < 5; ++k) {
        const int m = k * TPB2 + tid;
        const bool active = (m < HALF);
        int t = 0;
        if (active) { t = m + (HALF - 1); if (t >= HALF) t -= HALF; }  // bijection

        float xp = 0.f, yp = 0.f, xpp = 0.f, ypp = 0.f;

        if (active) {
            const float x = alpha[t];
            const float s = fmaf(x, INVXH, -1.0f);
            const float twos = s + s;
            const u64 TWOS = pack2(twos, twos);

            // Clenshaw (packed): b_k = c_k - b_{k+2} + 2s*b_{k+1}
            u64 bAx = 0ull, bAz = 0ull;   // b_{k+1}: (x,y) and (z,w) lanes
            u64 bBx = 0ull, bBz = 0ull;   // b_{k+2}
            const ulonglong2* cp = reinterpret_cast<const ulonglong2*>(coef);
            #pragma unroll
            for (int kk = NQ - 1; kk >= 1; --kk) {
                const ulonglong2 c = cp[kk];
                const u64 tx = fma2(bBx, NEG1, c.x);    // c - bB
                const u64 tz = fma2(bBz, NEG1, c.y);
                const u64 nx = fma2(TWOS, bAx, tx);
                const u64 nz = fma2(TWOS, bAz, tz);
                bBx = bAx;  bBz = bAz;
                bAx = nx;   bAz = nz;
            }
            const float4 c0 = coef[0];
            const float2 aX = unpack2(bAx), aZ = unpack2(bAz);
            const float2 bX = unpack2(bBx), bZ = unpack2(bBz);
            const float p0 = fmaf(s, aX.x, c0.x - bX.x);
            const float p1 = fmaf(s, aX.y, c0.y - bX.y);
            const float q0 = fmaf(s, aZ.x, c0.z - bZ.x);
            const float q1 = fmaf(s, aZ.y, c0.w - bZ.y);

            // square + JVP of square
            const float a  = p0 * p0;
            const float b  = p1 * p1;
            const float da = 2.0f * p0 * q0;
            const float db = 2.0f * p1 * q1;

            // trig epilogue (cos(x)-1 = -2*sin^2(x/2), cancellation-free)
            const float s2v = __sinf(0.5f * x);
            const float cm1 = -2.0f * s2v * s2v;
            const float sa  = __sinf(x);
            const float ca  = 1.0f + cm1;

            xp  = a * cm1;
            yp  = b * sa;
            xpp = fmaf(da, cm1, -a * sa);
            ypp = fmaf(db, sa,  b * ca);

            out[           row + t] = xp;
            out[AR       + row + t] = yp;
            out[2 * AR   + row + t] = xpp;
            out[3 * AR   + row + t] = ypp;

            if (t == HALF - 1) xlast_s = xp;   // only (k=0, tid=0)
        }

        if (k == 0) {            // uniform branch: all threads participate
            __syncthreads();
            xlast = xlast_s;
        }

        // mirror writes: dest col 2048 - t for t in 0..1023
        if (active && t < HALF - 1) {
            const int c2 = (NCOL - 1) - t;
            out[           row + c2] = 2.0f * xlast - xp;
            out[AR       + row + c2] = yp;
            out[2 * AR   + row + c2] = xpp;
            out[3 * AR   + row + c2] = -ypp;
        }
    }
}

extern "C" void kernel_launch(void* const* d_in, const int* in_sizes, int n_in,
                              void* d_out, int out_size)
{
    const float* alpha = (const float*)d_in[0];
    const float* w0    = (const float*)d_in[1];
    const float* w1    = (const float*)d_in[2];
    const float* w2    = (const float*)d_in[3];
    const float* b0    = (const float*)d_in[4];
    const float* b1    = (const float*)d_in[5];
    const float* b2    = (const float*)d_in[6];
    float* out = (float*)d_out;

    sofanet_coef_kernel<<<NAB, TPB>>>(w0, w1, w2, b0, b1, b2);
    sofanet_eval_kernel<<<NAB, TPB2>>>(alpha, out);
}

// round 9
// speedup vs baseline: 2.2059x; 2.2059x over previous
#include <cuda_runtime.h>

// SofaNetEllipse via Chebyshev spectral compression (NQ=32) — two kernels.
//
// Kernel A: exact MLP+JVP at 32 Chebyshev nodes per network, 2 threads/node
//           (TPB=64; warp pattern = 16 nodes x 2 halves, near-broadcast w1
//           reads — the R7-proven mapping) + DCT -> 32 float4 coeffs/network.
// Kernel B: Clenshaw (31 iters, packed fma.rn.f32x2) at all 1025 columns +
//           square/JVP + trig epilogue + mirror (unchanged, 18.7us proven).

#define NAB   1024
#define NCOL  2049
#define HALF  1025
#define H     64
#define TPBA  64      // kernel A
#define TPB2  256     // kernel B
#define NQ    32      // Chebyshev nodes / coefficients

#define XH    0.7853981633974483f   // pi/4  (half-width of [0, pi/2])
#define INVXH 1.2732395447351628f   // 4/pi  (s = alpha*INVXH - 1)

typedef unsigned long long u64;

__device__ __align__(16) float4 g_coef[NAB * NQ];   // 512 KB scratch

__device__ __forceinline__ float fast_tanh(float x) {
    // tanh(x) = 1 - 2/(exp(2x)+1); abs err ~1e-6, saturates correctly.
    float e = __expf(x + x);
    return 1.0f - __fdividef(2.0f, e + 1.0f);
}

__device__ __forceinline__ u64 fma2(u64 a, u64 b, u64 c) {
    u64 d;
    asm("fma.rn.f32x2 %0, %1, %2, %3;" : "=l"(d) : "l"(a), "l"(b), "l"(c));
    return d;
}
__device__ __forceinline__ u64 pack2(float lo, float hi) {
    u64 r;
    asm("mov.b64 %0, {%1, %2};" : "=l"(r) : "f"(lo), "f"(hi));
    return r;
}
__device__ __forceinline__ float2 unpack2(u64 v) {
    float2 r;
    asm("mov.b64 {%0, %1}, %2;" : "=f"(r.x), "=f"(r.y) : "l"(v));
    return r;
}

// ======================= Kernel A: coefficients =======================
__global__ __launch_bounds__(TPBA)
void sofanet_coef_kernel(const float* __restrict__ w0,
                         const float* __restrict__ w1,
                         const float* __restrict__ w2,
                         const float* __restrict__ b0,
                         const float* __restrict__ b1,
                         const float* __restrict__ b2)
{
    const int n   = blockIdx.x;   // network id
    const int tid = threadIdx.x;

    __shared__ __align__(16) float  w1s[H * H];   // 16 KB
    __shared__ float w0s[H], b0s[H], b1s[H];
    __shared__ float w2s[2 * H];
    __shared__ float b2s[2];
    __shared__ __align__(16) float4 nodes[NQ];    // f(x_q) = (p0,p1,q0,q1)

    // ---- stage weights ----
    {
        const float4* src = reinterpret_cast<const float4*>(w1 + (size_t)n * H * H);
        float4* dst = reinterpret_cast<float4*>(w1s);
        #pragma unroll
        for (int i = tid; i < (H * H) / 4; i += TPBA) dst[i] = src[i];

        w0s[tid] = w0[(size_t)n * H + tid];
        b0s[tid] = b0[(size_t)n * H + tid];
        b1s[tid] = b1[(size_t)n * H + tid];
        w2s[tid]      = w2[(size_t)n * 2 * H + tid];
        w2s[tid + 64] = w2[(size_t)n * 2 * H + tid + 64];
        if (tid < 2) b2s[tid] = b2[(size_t)n * 2 + tid];
    }
    __syncthreads();

    // ---- exact MLP + JVP at 32 Chebyshev nodes (2 threads per node) ----
    {
        const int q    = tid >> 1;        // node 0..31
        const int half = tid & 1;         // row half
        const float theta = (2 * q + 1) * (3.14159265358979323846f / 64.0f);
        const float xq = XH * (1.0f + cosf(theta));   // node in [0, pi/2]

        float h1[H], d1[H];
        #pragma unroll
        for (int j = 0; j < H; ++j) {
            const float w  = w0s[j];
            const float th = fast_tanh(fmaf(w, xq, b0s[j]));
            h1[j] = th;
            d1[j] = (1.0f - th * th) * w;
        }

        float p0 = 0.f, p1 = 0.f, q0 = 0.f, q1 = 0.f;
        const int i0 = half * 32;
        #pragma unroll 2
        for (int i = i0; i < i0 + 32; ++i) {
            float u = b1s[i], v = 0.f;
            const float* ra = &w1s[i * H];
            #pragma unroll
            for (int j = 0; j < H; j += 4) {
                const float4 wa = *reinterpret_cast<const float4*>(ra + j);
                u = fmaf(wa.x, h1[j    ], u);
                u = fmaf(wa.y, h1[j + 1], u);
                u = fmaf(wa.z, h1[j + 2], u);
                u = fmaf(wa.w, h1[j + 3], u);
                v = fmaf(wa.x, d1[j    ], v);
                v = fmaf(wa.y, d1[j + 1], v);
                v = fmaf(wa.z, d1[j + 2], v);
                v = fmaf(wa.w, d1[j + 3], v);
            }
            const float th = fast_tanh(u);
            const float dd = (1.0f - th * th) * v;
            p0 = fmaf(w2s[i    ], th, p0);
            p1 = fmaf(w2s[H + i], th, p1);
            q0 = fmaf(w2s[i    ], dd, q0);
            q1 = fmaf(w2s[H + i], dd, q1);
        }

        // combine the two halves (adjacent lanes, same warp)
        p0 += __shfl_xor_sync(0xFFFFFFFFu, p0, 1);
        p1 += __shfl_xor_sync(0xFFFFFFFFu, p1, 1);
        q0 += __shfl_xor_sync(0xFFFFFFFFu, q0, 1);
        q1 += __shfl_xor_sync(0xFFFFFFFFu, q1, 1);

        if (half == 0)
            nodes[q] = make_float4(p0 + b2s[0], p1 + b2s[1], q0, q1);
    }
    __syncthreads();

    // ---- DCT -> Chebyshev coefficients (threads 0..31) -> global ----
    if (tid < NQ) {
        const int k = tid;
        float s0 = 0.f, s1 = 0.f, s2 = 0.f, s3 = 0.f;
        #pragma unroll 8
        for (int q = 0; q < NQ; ++q) {
            const int m = (k * (2 * q + 1)) & 127;   // angle mod 2*pi
            const float c = __cosf((float)m * (3.14159265358979323846f / 64.0f));
            const float4 f = nodes[q];
            s0 = fmaf(c, f.x, s0);
            s1 = fmaf(c, f.y, s1);
            s2 = fmaf(c, f.z, s2);
            s3 = fmaf(c, f.w, s3);
        }
        const float sc = (k == 0) ? (1.0f / NQ) : (2.0f / NQ);
        g_coef[n * NQ + k] = make_float4(s0 * sc, s1 * sc, s2 * sc, s3 * sc);
    }
}

// ======================= Kernel B: evaluation =========================
__global__ __launch_bounds__(TPB2, 6)
void sofanet_eval_kernel(const float* __restrict__ alpha,
                         float* __restrict__ out)
{
    const int n   = blockIdx.x;   // network id
    const int tid = threadIdx.x;

    __shared__ __align__(16) float4 coef[NQ];   // 512 B
    __shared__ float xlast_s;

    // stage coefficients (128 floats, coalesced)
    if (tid < NQ * 4) {
        const float* src = (const float*)(g_coef + (size_t)n * NQ);
        ((float*)coef)[tid] = src[tid];
    }
    __syncthreads();

    const size_t AR  = (size_t)NAB * NCOL;
    const size_t row = (size_t)n * NCOL;
    float xlast = 0.0f;
    (void)xlast;

    const u64 NEG1 = pack2(-1.0f, -1.0f);

    // 5 strided tiles cover m = 0..1024 (TPB2=256); remap so m=0 -> t=1024.
    for (int k = 0; k < 5; ++k) {
        const int m = k * TPB2 + tid;
        const bool active = (m < HALF);
        int t = 0;
        if (active) { t = m + (HALF - 1); if (t >= HALF) t -= HALF; }  // bijection

        float xp = 0.f, yp = 0.f, xpp = 0.f, ypp = 0.f;

        if (active) {
            const float x = alpha[t];
            const float s = fmaf(x, INVXH, -1.0f);
            const float twos = s + s;
            const u64 TWOS = pack2(twos, twos);

            // Clenshaw (packed): b_k = c_k - b_{k+2} + 2s*b_{k+1}
            u64 bAx = 0ull, bAz = 0ull;   // b_{k+1}: (x,y) and (z,w) lanes
            u64 bBx = 0ull, bBz = 0ull;   // b_{k+2}
            const ulonglong2* cp = reinterpret_cast<const ulonglong2*>(coef);
            #pragma unroll
            for (int kk = NQ - 1; kk >= 1; --kk) {
                const ulonglong2 c = cp[kk];
                const u64 tx = fma2(bBx, NEG1, c.x);    // c - bB
                const u64 tz = fma2(bBz, NEG1, c.y);
                const u64 nx = fma2(TWOS, bAx, tx);
                const u64 nz = fma2(TWOS, bAz, tz);
                bBx = bAx;  bBz = bAz;
                bAx = nx;   bAz = nz;
            }
            const float4 c0 = coef[0];
            const float2 aX = unpack2(bAx), aZ = unpack2(bAz);
            const float2 bX = unpack2(bBx), bZ = unpack2(bBz);
            const float p0 = fmaf(s, aX.x, c0.x - bX.x);
            const float p1 = fmaf(s, aX.y, c0.y - bX.y);
            const float q0 = fmaf(s, aZ.x, c0.z - bZ.x);
            const float q1 = fmaf(s, aZ.y, c0.w - bZ.y);

            // square + JVP of square
            const float a  = p0 * p0;
            const float b  = p1 * p1;
            const float da = 2.0f * p0 * q0;
            const float db = 2.0f * p1 * q1;

            // trig epilogue (cos(x)-1 = -2*sin^2(x/2), cancellation-free)
            const float s2v = __sinf(0.5f * x);
            const float cm1 = -2.0f * s2v * s2v;
            const float sa  = __sinf(x);
            const float ca  = 1.0f + cm1;

            xp  = a * cm1;
            yp  = b * sa;
            xpp = fmaf(da, cm1, -a * sa);
            ypp = fmaf(db, sa,  b * ca);

            out[           row + t] = xp;
            out[AR       + row + t] = yp;
            out[2 * AR   + row + t] = xpp;
            out[3 * AR   + row + t] = ypp;

            if (t == HALF - 1) xlast_s = xp;   // only (k=0, tid=0)
        }

        if (k == 0) {            // uniform branch: all threads participate
            __syncthreads();
            xlast = xlast_s;
        }

        // mirror writes: dest col 2048 - t for t in 0..1023
        if (active && t < HALF - 1) {
            const int c2 = (NCOL - 1) - t;
            out[           row + c2] = 2.0f * xlast - xp;
            out[AR       + row + c2] = yp;
            out[2 * AR   + row + c2] = xpp;
            out[3 * AR   + row + c2] = -ypp;
        }
    }
}

extern "C" void kernel_launch(void* const* d_in, const int* in_sizes, int n_in,
                              void* d_out, int out_size)
{
    const float* alpha = (const float*)d_in[0];
    const float* w0    = (const float*)d_in[1];
    const float* w1    = (const float*)d_in[2];
    const float* w2    = (const float*)d_in[3];
    const float* b0    = (const float*)d_in[4];
    const float* b1    = (const float*)d_in[5];
    const float* b2    = (const float*)d_in[6];
    float* out = (float*)d_out;

    sofanet_coef_kernel<<<NAB, TPBA>>>(w0, w1, w2, b0, b1, b2);
    sofanet_eval_kernel<<<NAB, TPB2>>>(alpha, out);
}

// round 11
// speedup vs baseline: 2.3162x; 1.0500x over previous
#include <cuda_runtime.h>

// SofaNetEllipse via Chebyshev spectral compression (NQ=24) — two kernels.
//
// Kernel A: exact MLP+JVP at 24 Chebyshev nodes per network, 2 threads/node
//           (near-broadcast w1 mapping). ALL 64 threads run the node block
//           (q clamped; lanes 48-63 redundant) so __shfl_xor_sync's full mask
//           is legal — the R10 guard deadlocked warp 1.
// Kernel B: Clenshaw (23 iters, packed fma.rn.f32x2), 2 columns per thread
//           (4 independent chains interleaved) + square/JVP + trig + mirror.

#define NAB   1024
#define NCOL  2049
#define HALF  1025
#define H     64
#define TPBA  64      // kernel A
#define TPB2  256     // kernel B
#define NQ    24      // Chebyshev nodes / coefficients

#define XH    0.7853981633974483f   // pi/4  (half-width of [0, pi/2])
#define INVXH 1.2732395447351628f   // 4/pi  (s = alpha*INVXH - 1)

typedef unsigned long long u64;

__device__ __align__(16) float4 g_coef[NAB * NQ];   // 384 KB scratch

__device__ __forceinline__ float fast_tanh(float x) {
    // tanh(x) = 1 - 2/(exp(2x)+1); abs err ~1e-6, saturates correctly.
    float e = __expf(x + x);
    return 1.0f - __fdividef(2.0f, e + 1.0f);
}

__device__ __forceinline__ u64 fma2(u64 a, u64 b, u64 c) {
    u64 d;
    asm("fma.rn.f32x2 %0, %1, %2, %3;" : "=l"(d) : "l"(a), "l"(b), "l"(c));
    return d;
}
__device__ __forceinline__ u64 pack2(float lo, float hi) {
    u64 r;
    asm("mov.b64 %0, {%1, %2};" : "=l"(r) : "f"(lo), "f"(hi));
    return r;
}
__device__ __forceinline__ float2 unpack2(u64 v) {
    float2 r;
    asm("mov.b64 {%0, %1}, %2;" : "=f"(r.x), "=f"(r.y) : "l"(v));
    return r;
}

// ======================= Kernel A: coefficients =======================
__global__ __launch_bounds__(TPBA)
void sofanet_coef_kernel(const float* __restrict__ w0,
                         const float* __restrict__ w1,
                         const float* __restrict__ w2,
                         const float* __restrict__ b0,
                         const float* __restrict__ b1,
                         const float* __restrict__ b2)
{
    const int n   = blockIdx.x;   // network id
    const int tid = threadIdx.x;

    __shared__ __align__(16) float  w1s[H * H];   // 16 KB
    __shared__ float w0s[H], b0s[H], b1s[H];
    __shared__ float w2s[2 * H];
    __shared__ float b2s[2];
    __shared__ __align__(16) float4 nodes[NQ];    // f(x_q) = (p0,p1,q0,q1)

    // ---- stage weights ----
    {
        const float4* src = reinterpret_cast<const float4*>(w1 + (size_t)n * H * H);
        float4* dst = reinterpret_cast<float4*>(w1s);
        #pragma unroll
        for (int i = tid; i < (H * H) / 4; i += TPBA) dst[i] = src[i];

        w0s[tid] = w0[(size_t)n * H + tid];
        b0s[tid] = b0[(size_t)n * H + tid];
        b1s[tid] = b1[(size_t)n * H + tid];
        w2s[tid]      = w2[(size_t)n * 2 * H + tid];
        w2s[tid + 64] = w2[(size_t)n * 2 * H + tid + 64];
        if (tid < 2) b2s[tid] = b2[(size_t)n * 2 + tid];
    }
    __syncthreads();

    // ---- exact MLP + JVP at 24 Chebyshev nodes (2 threads per node) ----
    // ALL threads execute (q clamped) so full-mask shfl is warp-uniform.
    {
        const int qraw = tid >> 1;                         // 0..31
        const int q    = (qraw < NQ) ? qraw : (NQ - 1);    // clamp; 48-63 redundant
        const int half = tid & 1;                          // row half
        const float theta = (2 * q + 1) * (3.14159265358979323846f / (2.0f * NQ));
        const float xq = XH * (1.0f + cosf(theta));        // node in [0, pi/2]

        float h1[H], d1[H];
        #pragma unroll
        for (int j = 0; j < H; ++j) {
            const float w  = w0s[j];
            const float th = fast_tanh(fmaf(w, xq, b0s[j]));
            h1[j] = th;
            d1[j] = (1.0f - th * th) * w;
        }

        float p0 = 0.f, p1 = 0.f, q0 = 0.f, q1 = 0.f;
        const int i0 = half * 32;
        #pragma unroll 2
        for (int i = i0; i < i0 + 32; ++i) {
            float u = b1s[i], v = 0.f;
            const float* ra = &w1s[i * H];
            #pragma unroll
            for (int j = 0; j < H; j += 4) {
                const float4 wa = *reinterpret_cast<const float4*>(ra + j);
                u = fmaf(wa.x, h1[j    ], u);
                u = fmaf(wa.y, h1[j + 1], u);
                u = fmaf(wa.z, h1[j + 2], u);
                u = fmaf(wa.w, h1[j + 3], u);
                v = fmaf(wa.x, d1[j    ], v);
                v = fmaf(wa.y, d1[j + 1], v);
                v = fmaf(wa.z, d1[j + 2], v);
                v = fmaf(wa.w, d1[j + 3], v);
            }
            const float th = fast_tanh(u);
            const float dd = (1.0f - th * th) * v;
            p0 = fmaf(w2s[i    ], th, p0);
            p1 = fmaf(w2s[H + i], th, p1);
            q0 = fmaf(w2s[i    ], dd, q0);
            q1 = fmaf(w2s[H + i], dd, q1);
        }

        // combine the two halves (adjacent lanes, same warp, all lanes active)
        p0 += __shfl_xor_sync(0xFFFFFFFFu, p0, 1);
        p1 += __shfl_xor_sync(0xFFFFFFFFu, p1, 1);
        q0 += __shfl_xor_sync(0xFFFFFFFFu, q0, 1);
        q1 += __shfl_xor_sync(0xFFFFFFFFu, q1, 1);

        if (half == 0 && qraw < NQ)
            nodes[q] = make_float4(p0 + b2s[0], p1 + b2s[1], q0, q1);
    }
    __syncthreads();

    // ---- DCT -> Chebyshev coefficients (threads 0..23) -> global ----
    if (tid < NQ) {
        const int k = tid;
        float s0 = 0.f, s1 = 0.f, s2 = 0.f, s3 = 0.f;
        #pragma unroll
        for (int q = 0; q < NQ; ++q) {
            const int m = (k * (2 * q + 1)) % (4 * NQ);   // angle mod 2*pi
            const float c = __cosf((float)m * (3.14159265358979323846f / (2.0f * NQ)));
            const float4 f = nodes[q];
            s0 = fmaf(c, f.x, s0);
            s1 = fmaf(c, f.y, s1);
            s2 = fmaf(c, f.z, s2);
            s3 = fmaf(c, f.w, s3);
        }
        const float sc = (k == 0) ? (1.0f / NQ) : (2.0f / NQ);
        g_coef[n * NQ + k] = make_float4(s0 * sc, s1 * sc, s2 * sc, s3 * sc);
    }
}

// ======================= Kernel B: evaluation =========================

// Single-column Clenshaw + epilogue (results returned; no memory side effects).
__device__ __forceinline__ void eval_col(const float x, const float4* coef,
                                         float& xp, float& yp, float& xpp, float& ypp)
{
    const u64 NEG1 = pack2(-1.0f, -1.0f);
    const float s = fmaf(x, INVXH, -1.0f);
    const float twos = s + s;
    const u64 TWOS = pack2(twos, twos);

    u64 bAx = 0ull, bAz = 0ull, bBx = 0ull, bBz = 0ull;
    const ulonglong2* cp = reinterpret_cast<const ulonglong2*>(coef);
    #pragma unroll
    for (int kk = NQ - 1; kk >= 1; --kk) {
        const ulonglong2 c = cp[kk];
        const u64 nx = fma2(TWOS, bAx, fma2(bBx, NEG1, c.x));
        const u64 nz = fma2(TWOS, bAz, fma2(bBz, NEG1, c.y));
        bBx = bAx;  bBz = bAz;
        bAx = nx;   bAz = nz;
    }
    const float4 c0 = coef[0];
    const float2 aX = unpack2(bAx), aZ = unpack2(bAz);
    const float2 bX = unpack2(bBx), bZ = unpack2(bBz);
    const float p0 = fmaf(s, aX.x, c0.x - bX.x);
    const float p1 = fmaf(s, aX.y, c0.y - bX.y);
    const float q0 = fmaf(s, aZ.x, c0.z - bZ.x);
    const float q1 = fmaf(s, aZ.y, c0.w - bZ.y);

    const float a  = p0 * p0;
    const float b  = p1 * p1;
    const float da = 2.0f * p0 * q0;
    const float db = 2.0f * p1 * q1;

    const float s2v = __sinf(0.5f * x);
    const float cm1 = -2.0f * s2v * s2v;    // cos(x)-1
    const float sa  = __sinf(x);
    const float ca  = 1.0f + cm1;

    xp  = a * cm1;
    yp  = b * sa;
    xpp = fmaf(da, cm1, -a * sa);
    ypp = fmaf(db, sa,  b * ca);
}

// Dual-column version: two independent Clenshaw chains interleaved, sharing
// each coefficient LDS.128 — doubles ILP where the kernel is latency-bound.
__device__ __forceinline__ void eval_col2(const float x1, const float x2,
                                          const float4* coef,
                                          float4& r1, float4& r2)
{
    const u64 NEG1 = pack2(-1.0f, -1.0f);
    const float s1 = fmaf(x1, INVXH, -1.0f);
    const float s2 = fmaf(x2, INVXH, -1.0f);
    const u64 T1 = pack2(s1 + s1, s1 + s1);
    const u64 T2 = pack2(s2 + s2, s2 + s2);

    u64 aX1 = 0ull, aZ1 = 0ull, bX1 = 0ull, bZ1 = 0ull;
    u64 aX2 = 0ull, aZ2 = 0ull, bX2 = 0ull, bZ2 = 0ull;
    const ulonglong2* cp = reinterpret_cast<const ulonglong2*>(coef);
    #pragma unroll
    for (int kk = NQ - 1; kk >= 1; --kk) {
        const ulonglong2 c = cp[kk];
        const u64 n1x = fma2(T1, aX1, fma2(bX1, NEG1, c.x));
        const u64 n2x = fma2(T2, aX2, fma2(bX2, NEG1, c.x));
        const u64 n1z = fma2(T1, aZ1, fma2(bZ1, NEG1, c.y));
        const u64 n2z = fma2(T2, aZ2, fma2(bZ2, NEG1, c.y));
        bX1 = aX1;  bZ1 = aZ1;  bX2 = aX2;  bZ2 = aZ2;
        aX1 = n1x;  aZ1 = n1z;  aX2 = n2x;  aZ2 = n2z;
    }
    const float4 c0 = coef[0];
    {
        const float2 aX = unpack2(aX1), aZ = unpack2(aZ1);
        const float2 bX = unpack2(bX1), bZ = unpack2(bZ1);
        const float p0 = fmaf(s1, aX.x, c0.x - bX.x);
        const float p1 = fmaf(s1, aX.y, c0.y - bX.y);
        const float q0 = fmaf(s1, aZ.x, c0.z - bZ.x);
        const float q1 = fmaf(s1, aZ.y, c0.w - bZ.y);
        const float a  = p0 * p0, b = p1 * p1;
        const float da = 2.0f * p0 * q0, db = 2.0f * p1 * q1;
        const float sv = __sinf(0.5f * x1);
        const float cm1 = -2.0f * sv * sv;
        const float sa  = __sinf(x1);
        r1.x = a * cm1;
        r1.y = b * sa;
        r1.z = fmaf(da, cm1, -a * sa);
        r1.w = fmaf(db, sa, b * (1.0f + cm1));
    }
    {
        const float2 aX = unpack2(aX2), aZ = unpack2(aZ2);
        const float2 bX = unpack2(bX2), bZ = unpack2(bZ2);
        const float p0 = fmaf(s2, aX.x, c0.x - bX.x);
        const float p1 = fmaf(s2, aX.y, c0.y - bX.y);
        const float q0 = fmaf(s2, aZ.x, c0.z - bZ.x);
        const float q1 = fmaf(s2, aZ.y, c0.w - bZ.y);
        const float a  = p0 * p0, b = p1 * p1;
        const float da = 2.0f * p0 * q0, db = 2.0f * p1 * q1;
        const float sv = __sinf(0.5f * x2);
        const float cm1 = -2.0f * sv * sv;
        const float sa  = __sinf(x2);
        r2.x = a * cm1;
        r2.y = b * sa;
        r2.z = fmaf(da, cm1, -a * sa);
        r2.w = fmaf(db, sa, b * (1.0f + cm1));
    }
}

__global__ __launch_bounds__(TPB2)
void sofanet_eval_kernel(const float* __restrict__ alpha,
                         float* __restrict__ out)
{
    const int n   = blockIdx.x;   // network id
    const int tid = threadIdx.x;

    __shared__ __align__(16) float4 coef[NQ];   // 384 B
    __shared__ float xlast_s;

    // stage coefficients (96 floats, coalesced)
    if (tid < NQ * 4) {
        const float* src = (const float*)(g_coef + (size_t)n * NQ);
        ((float*)coef)[tid] = src[tid];
    }
    __syncthreads();

    const size_t AR  = (size_t)NAB * NCOL;
    const size_t row = (size_t)n * NCOL;
    float xlast = 0.0f;

    // Column mapping (bijection): m=0 -> t=1024, m>=1 -> t=m-1.
    // Pairs: k=0 covers m = tid, tid+256; k=1 covers m = tid+512, tid+768.
    // Tail m=1024 (t=1023) handled by thread 0 afterwards.
    #pragma unroll
    for (int k = 0; k < 2; ++k) {
        const int m1 = k * 512 + tid;
        const int m2 = m1 + 256;
        const int t1 = (m1 == 0) ? (HALF - 1) : (m1 - 1);
        const int t2 = m2 - 1;

        float4 r1, r2;
        eval_col2(alpha[t1], alpha[t2], coef, r1, r2);

        out[           row + t1] = r1.x;
        out[AR       + row + t1] = r1.y;
        out[2 * AR   + row + t1] = r1.z;
        out[3 * AR   + row + t1] = r1.w;
        out[           row + t2] = r2.x;
        out[AR       + row + t2] = r2.y;
        out[2 * AR   + row + t2] = r2.z;
        out[3 * AR   + row + t2] = r2.w;

        if (k == 0) {
            if (tid == 0) xlast_s = r1.x;     // t1 == 1024 for tid 0
            __syncthreads();                  // uniform: all threads, k==0
            xlast = xlast_s;
        }

        // mirror writes (t < 1024 only; for k=0 tid=0, t1==1024 is excluded)
        if (t1 < HALF - 1) {
            const int c2 = (NCOL - 1) - t1;
            out[           row + c2] = 2.0f * xlast - r1.x;
            out[AR       + row + c2] = r1.y;
            out[2 * AR   + row + c2] = r1.z;
            out[3 * AR   + row + c2] = -r1.w;
        }
        {
            const int c2 = (NCOL - 1) - t2;
            out[           row + c2] = 2.0f * xlast - r2.x;
            out[AR       + row + c2] = r2.y;
            out[2 * AR   + row + c2] = r2.z;
            out[3 * AR   + row + c2] = -r2.w;
        }
    }

    // tail column m=1024 -> t=1023
    if (tid == 0) {
        const int t = 1023;
        float xp, yp, xpp, ypp;
        eval_col(alpha[t], coef, xp, yp, xpp, ypp);
        out[           row + t] = xp;
        out[AR       + row + t] = yp;
        out[2 * AR   + row + t] = xpp;
        out[3 * AR   + row + t] = ypp;
        const int c2 = (NCOL - 1) - t;   // 1025
        out[           row + c2] = 2.0f * xlast - xp;
        out[AR       + row + c2] = yp;
        out[2 * AR   + row + c2] = xpp;
        out[3 * AR   + row + c2] = -ypp;
    }
}

extern "C" void kernel_launch(void* const* d_in, const int* in_sizes, int n_in,
                              void* d_out, int out_size)
{
    const float* alpha = (const float*)d_in[0];
    const float* w0    = (const float*)d_in[1];
    const float* w1    = (const float*)d_in[2];
    const float* w2    = (const float*)d_in[3];
    const float* b0    = (const float*)d_in[4];
    const float* b1    = (const float*)d_in[5];
    const float* b2    = (const float*)d_in[6];
    float* out = (float*)d_out;

    sofanet_coef_kernel<<<NAB, TPBA>>>(w0, w1, w2, b0, b1, b2);
    sofanet_eval_kernel<<<NAB, TPB2>>>(alpha, out);
}

// round 12
// speedup vs baseline: 3.5618x; 1.5378x over previous
#include <cuda_runtime.h>

// SofaNetEllipse via Chebyshev spectral compression (NQ=16) — two kernels.
//
// Kernel A: exact MLP+JVP at 16 Chebyshev nodes per network, 2 threads/node,
//           TPBA=32 (ONE full warp: every lane does useful work, full-mask
//           shfl is legal, zero redundant nodes). R9-proven structure.
// Kernel B: Clenshaw (15 iters, packed fma.rn.f32x2), single column/thread,
//           5 tiles (R9-proven 40-reg shape) + square/JVP + trig + mirror.

#define NAB   1024
#define NCOL  2049
#define HALF  1025
#define H     64
#define TPBA  32      // kernel A: one warp, 2 threads/node x 16 nodes
#define TPB2  256     // kernel B
#define NQ    16      // Chebyshev nodes / coefficients

#define XH    0.7853981633974483f   // pi/4  (half-width of [0, pi/2])
#define INVXH 1.2732395447351628f   // 4/pi  (s = alpha*INVXH - 1)

typedef unsigned long long u64;

__device__ __align__(16) float4 g_coef[NAB * NQ];   // 256 KB scratch

__device__ __forceinline__ float fast_tanh(float x) {
    // tanh(x) = 1 - 2/(exp(2x)+1); abs err ~1e-6, saturates correctly.
    float e = __expf(x + x);
    return 1.0f - __fdividef(2.0f, e + 1.0f);
}

__device__ __forceinline__ u64 fma2(u64 a, u64 b, u64 c) {
    u64 d;
    asm("fma.rn.f32x2 %0, %1, %2, %3;" : "=l"(d) : "l"(a), "l"(b), "l"(c));
    return d;
}
__device__ __forceinline__ u64 pack2(float lo, float hi) {
    u64 r;
    asm("mov.b64 %0, {%1, %2};" : "=l"(r) : "f"(lo), "f"(hi));
    return r;
}
__device__ __forceinline__ float2 unpack2(u64 v) {
    float2 r;
    asm("mov.b64 {%0, %1}, %2;" : "=f"(r.x), "=f"(r.y) : "l"(v));
    return r;
}

// ======================= Kernel A: coefficients =======================
__global__ __launch_bounds__(TPBA)
void sofanet_coef_kernel(const float* __restrict__ w0,
                         const float* __restrict__ w1,
                         const float* __restrict__ w2,
                         const float* __restrict__ b0,
                         const float* __restrict__ b1,
                         const float* __restrict__ b2)
{
    const int n   = blockIdx.x;   // network id
    const int tid = threadIdx.x;  // 0..31

    __shared__ __align__(16) float  w1s[H * H];   // 16 KB
    __shared__ float w0s[H], b0s[H], b1s[H];
    __shared__ float w2s[2 * H];
    __shared__ float b2s[2];
    __shared__ __align__(16) float4 nodes[NQ];    // f(x_q) = (p0,p1,q0,q1)

    // ---- stage weights (32 threads) ----
    {
        const float4* src = reinterpret_cast<const float4*>(w1 + (size_t)n * H * H);
        float4* dst = reinterpret_cast<float4*>(w1s);
        #pragma unroll
        for (int i = tid; i < (H * H) / 4; i += TPBA) dst[i] = src[i];

        w0s[tid]      = w0[(size_t)n * H + tid];
        w0s[tid + 32] = w0[(size_t)n * H + tid + 32];
        b0s[tid]      = b0[(size_t)n * H + tid];
        b0s[tid + 32] = b0[(size_t)n * H + tid + 32];
        b1s[tid]      = b1[(size_t)n * H + tid];
        b1s[tid + 32] = b1[(size_t)n * H + tid + 32];
        #pragma unroll
        for (int r = 0; r < 4; ++r)
            w2s[tid + 32 * r] = w2[(size_t)n * 2 * H + tid + 32 * r];
        if (tid < 2) b2s[tid] = b2[(size_t)n * 2 + tid];
    }
    __syncthreads();

    // ---- exact MLP + JVP at 16 Chebyshev nodes (2 threads per node) ----
    // One full warp: every lane useful, full-mask shfl legal.
    {
        const int q    = tid >> 1;        // node 0..15
        const int half = tid & 1;         // row half
        const float theta = (2 * q + 1) * (3.14159265358979323846f / (2.0f * NQ));
        const float xq = XH * (1.0f + cosf(theta));   // node in [0, pi/2]

        float h1[H], d1[H];
        #pragma unroll
        for (int j = 0; j < H; ++j) {
            const float w  = w0s[j];
            const float th = fast_tanh(fmaf(w, xq, b0s[j]));
            h1[j] = th;
            d1[j] = (1.0f - th * th) * w;
        }

        float p0 = 0.f, p1 = 0.f, q0 = 0.f, q1 = 0.f;
        const int i0 = half * 32;
        #pragma unroll 2
        for (int i = i0; i < i0 + 32; ++i) {
            float u = b1s[i], v = 0.f;
            const float* ra = &w1s[i * H];
            #pragma unroll
            for (int j = 0; j < H; j += 4) {
                const float4 wa = *reinterpret_cast<const float4*>(ra + j);
                u = fmaf(wa.x, h1[j    ], u);
                u = fmaf(wa.y, h1[j + 1], u);
                u = fmaf(wa.z, h1[j + 2], u);
                u = fmaf(wa.w, h1[j + 3], u);
                v = fmaf(wa.x, d1[j    ], v);
                v = fmaf(wa.y, d1[j + 1], v);
                v = fmaf(wa.z, d1[j + 2], v);
                v = fmaf(wa.w, d1[j + 3], v);
            }
            const float th = fast_tanh(u);
            const float dd = (1.0f - th * th) * v;
            p0 = fmaf(w2s[i    ], th, p0);
            p1 = fmaf(w2s[H + i], th, p1);
            q0 = fmaf(w2s[i    ], dd, q0);
            q1 = fmaf(w2s[H + i], dd, q1);
        }

        // combine the two halves (adjacent lanes, same warp, all lanes active)
        p0 += __shfl_xor_sync(0xFFFFFFFFu, p0, 1);
        p1 += __shfl_xor_sync(0xFFFFFFFFu, p1, 1);
        q0 += __shfl_xor_sync(0xFFFFFFFFu, q0, 1);
        q1 += __shfl_xor_sync(0xFFFFFFFFu, q1, 1);

        if (half == 0)
            nodes[q] = make_float4(p0 + b2s[0], p1 + b2s[1], q0, q1);
    }
    __syncthreads();

    // ---- DCT -> Chebyshev coefficients (threads 0..15) -> global ----
    if (tid < NQ) {
        const int k = tid;
        float s0 = 0.f, s1 = 0.f, s2 = 0.f, s3 = 0.f;
        #pragma unroll
        for (int q = 0; q < NQ; ++q) {
            const int m = (k * (2 * q + 1)) & (4 * NQ - 1);   // angle mod 2*pi (64 = pow2)
            const float c = __cosf((float)m * (3.14159265358979323846f / (2.0f * NQ)));
            const float4 f = nodes[q];
            s0 = fmaf(c, f.x, s0);
            s1 = fmaf(c, f.y, s1);
            s2 = fmaf(c, f.z, s2);
            s3 = fmaf(c, f.w, s3);
        }
        const float sc = (k == 0) ? (1.0f / NQ) : (2.0f / NQ);
        g_coef[n * NQ + k] = make_float4(s0 * sc, s1 * sc, s2 * sc, s3 * sc);
    }
}

// ======================= Kernel B: evaluation =========================
__global__ __launch_bounds__(TPB2, 6)
void sofanet_eval_kernel(const float* __restrict__ alpha,
                         float* __restrict__ out)
{
    const int n   = blockIdx.x;   // network id
    const int tid = threadIdx.x;

    __shared__ __align__(16) float4 coef[NQ];   // 256 B
    __shared__ float xlast_s;

    // stage coefficients (64 floats, coalesced)
    if (tid < NQ * 4) {
        const float* src = (const float*)(g_coef + (size_t)n * NQ);
        ((float*)coef)[tid] = src[tid];
    }
    __syncthreads();

    const size_t AR  = (size_t)NAB * NCOL;
    const size_t row = (size_t)n * NCOL;
    float xlast = 0.0f;
    (void)xlast;

    const u64 NEG1 = pack2(-1.0f, -1.0f);

    // 5 strided tiles cover m = 0..1024 (TPB2=256); remap so m=0 -> t=1024.
    for (int k = 0; k < 5; ++k) {
        const int m = k * TPB2 + tid;
        const bool active = (m < HALF);
        int t = 0;
        if (active) { t = m + (HALF - 1); if (t >= HALF) t -= HALF; }  // bijection

        float xp = 0.f, yp = 0.f, xpp = 0.f, ypp = 0.f;

        if (active) {
            const float x = alpha[t];
            const float s = fmaf(x, INVXH, -1.0f);
            const float twos = s + s;
            const u64 TWOS = pack2(twos, twos);

            // Clenshaw (packed): b_k = c_k - b_{k+2} + 2s*b_{k+1}
            u64 bAx = 0ull, bAz = 0ull;   // b_{k+1}: (x,y) and (z,w) lanes
            u64 bBx = 0ull, bBz = 0ull;   // b_{k+2}
            const ulonglong2* cp = reinterpret_cast<const ulonglong2*>(coef);
            #pragma unroll
            for (int kk = NQ - 1; kk >= 1; --kk) {
                const ulonglong2 c = cp[kk];
                const u64 nx = fma2(TWOS, bAx, fma2(bBx, NEG1, c.x));
                const u64 nz = fma2(TWOS, bAz, fma2(bBz, NEG1, c.y));
                bBx = bAx;  bBz = bAz;
                bAx = nx;   bAz = nz;
            }
            const float4 c0 = coef[0];
            const float2 aX = unpack2(bAx), aZ = unpack2(bAz);
            const float2 bX = unpack2(bBx), bZ = unpack2(bBz);
            const float p0 = fmaf(s, aX.x, c0.x - bX.x);
            const float p1 = fmaf(s, aX.y, c0.y - bX.y);
            const float q0 = fmaf(s, aZ.x, c0.z - bZ.x);
            const float q1 = fmaf(s, aZ.y, c0.w - bZ.y);

            // square + JVP of square
            const float a  = p0 * p0;
            const float b  = p1 * p1;
            const float da = 2.0f * p0 * q0;
            const float db = 2.0f * p1 * q1;

            // trig epilogue (cos(x)-1 = -2*sin^2(x/2), cancellation-free)
            const float s2v = __sinf(0.5f * x);
            const float cm1 = -2.0f * s2v * s2v;
            const float sa  = __sinf(x);
            const float ca  = 1.0f + cm1;

            xp  = a * cm1;
            yp  = b * sa;
            xpp = fmaf(da, cm1, -a * sa);
            ypp = fmaf(db, sa,  b * ca);

            out[           row + t] = xp;
            out[AR       + row + t] = yp;
            out[2 * AR   + row + t] = xpp;
            out[3 * AR   + row + t] = ypp;

            if (t == HALF - 1) xlast_s = xp;   // only (k=0, tid=0)
        }

        if (k == 0) {            // uniform branch: all threads participate
            __syncthreads();
            xlast = xlast_s;
        }

        // mirror writes: dest col 2048 - t for t in 0..1023
        if (active && t < HALF - 1) {
            const int c2 = (NCOL - 1) - t;
            out[           row + c2] = 2.0f * xlast - xp;
            out[AR       + row + c2] = yp;
            out[2 * AR   + row + c2] = xpp;
            out[3 * AR   + row + c2] = -ypp;
        }
    }
}

extern "C" void kernel_launch(void* const* d_in, const int* in_sizes, int n_in,
                              void* d_out, int out_size)
{
    const float* alpha = (const float*)d_in[0];
    const float* w0    = (const float*)d_in[1];
    const float* w1    = (const float*)d_in[2];
    const float* w2    = (const float*)d_in[3];
    const float* b0    = (const float*)d_in[4];
    const float* b1    = (const float*)d_in[5];
    const float* b2    = (const float*)d_in[6];
    float* out = (float*)d_out;

    sofanet_coef_kernel<<<NAB, TPBA>>>(w0, w1, w2, b0, b1, b2);
    sofanet_eval_kernel<<<NAB, TPB2>>>(alpha, out);
}